// round 3
// baseline (speedup 1.0000x reference)
#include <cuda_runtime.h>
#include <cuda_bf16.h>
#include <math.h>

#define N_NODES 10000
#define N_EDGES 160000
#define N_GRAPH 64
#define HID     128
#define H2      256
#define N_LAYER 14

// ---------------- device scratch (no allocations allowed) ----------------
__device__ float g_h[N_NODES * HID];
__device__ float g_r[N_NODES * HID];
__device__ float g_rnorm[N_NODES];
__device__ float g_Q[N_NODES * HID];
__device__ float g_P[N_NODES * HID];
__device__ float g_out[N_NODES * HID];
__device__ float g_z1[N_NODES * H2];
__device__ float g_a[N_NODES * H2];
__device__ int   g_deg[N_NODES];
__device__ int   g_rowptr[N_NODES + 1];
__device__ int   g_cursor[N_NODES];
__device__ int   g_col[N_EDGES];
__device__ float g_gsum[N_GRAPH * HID];
__device__ float g_cnt[N_GRAPH];

// ---------------- helpers ----------------
__device__ __forceinline__ unsigned long long pack2(float lo, float hi) {
    unsigned long long r;
    asm("mov.b64 %0, {%1,%2};" : "=l"(r) : "f"(lo), "f"(hi));
    return r;
}
__device__ __forceinline__ void unpack2(unsigned long long v, float& lo, float& hi) {
    asm("mov.b64 {%0,%1}, %2;" : "=f"(lo), "=f"(hi) : "l"(v));
}
#define FMA_F32X2(d, a, b, c) \
    asm("fma.rn.f32x2 %0, %1, %2, %3;" : "=l"(d) : "l"(a), "l"(b), "l"(c))

// block-wide sum, result broadcast to all threads. blockDim.x multiple of 32, <=256.
__device__ __forceinline__ float blockSum(float v, float* s) {
    #pragma unroll
    for (int o = 16; o; o >>= 1) v += __shfl_down_sync(0xffffffffu, v, o);
    __syncthreads();
    if ((threadIdx.x & 31) == 0) s[threadIdx.x >> 5] = v;
    __syncthreads();
    int nw = blockDim.x >> 5;
    float t = 0.f;
    for (int i = 0; i < nw; i++) t += s[i];
    return t;
}

// ---------------- CSR construction ----------------
__global__ void zero_csr_kernel() {
    int i = blockIdx.x * blockDim.x + threadIdx.x;
    if (i < N_NODES) g_deg[i] = 0;
}
__global__ void csr_count_kernel(const int* __restrict__ ei) {
    int e = blockIdx.x * blockDim.x + threadIdx.x;
    if (e < N_EDGES) atomicAdd(&g_deg[ei[N_EDGES + e]], 1);
}
__global__ void scan_kernel() {
    __shared__ int s[1024];
    const int CH = 10;  // 1024*10 >= 10000
    int t = threadIdx.x;
    int base = t * CH;
    int local[CH];
    int sum = 0;
    #pragma unroll
    for (int j = 0; j < CH; j++) {
        int idx = base + j;
        int v = (idx < N_NODES) ? g_deg[idx] : 0;
        local[j] = sum;
        sum += v;
    }
    s[t] = sum;
    __syncthreads();
    for (int off = 1; off < 1024; off <<= 1) {
        int v = (t >= off) ? s[t - off] : 0;
        __syncthreads();
        s[t] += v;
        __syncthreads();
    }
    int offset = (t > 0) ? s[t - 1] : 0;
    #pragma unroll
    for (int j = 0; j < CH; j++) {
        int idx = base + j;
        if (idx < N_NODES) {
            g_rowptr[idx] = offset + local[j];
            g_cursor[idx] = offset + local[j];
        }
    }
    if (t == 1023) g_rowptr[N_NODES] = s[1023];
}
__global__ void csr_fill_kernel(const int* __restrict__ ei) {
    int e = blockIdx.x * blockDim.x + threadIdx.x;
    if (e < N_EDGES) {
        int d = ei[N_EDGES + e];
        int p = atomicAdd(&g_cursor[d], 1);
        g_col[p] = ei[e];
    }
}

// ---------------- generic fused GEMM: C = A@B + bias (+Cin) ----------------
// A: [M,K] row-major, B: [K,N] row-major. BM=64, BN=128, BK=16, 256 threads.
// Requires K%16==0, N%128==0. M guarded.
__global__ __launch_bounds__(256) void gemm_kernel(
    const float* __restrict__ A, const float* __restrict__ B,
    const float* __restrict__ bias, const float* __restrict__ Cin,
    float* __restrict__ Cout, int M, int N, int K)
{
    __shared__ float As[16][64];   // [k][m]
    __shared__ float Bs[16][128];  // [k][n]
    int tid = threadIdx.x;
    int bm = blockIdx.y * 64;
    int bn = blockIdx.x * 128;
    int tr = tid >> 5;        // 0..7
    int tc = tid & 31;        // 0..31
    int row0 = tr * 8, col0 = tc * 4;

    unsigned long long acc[8][2];
    #pragma unroll
    for (int i = 0; i < 8; i++) { acc[i][0] = 0ull; acc[i][1] = 0ull; }

    int a_row = tid >> 2;          // 0..63
    int a_col = (tid & 3) * 4;     // 0,4,8,12

    for (int k0 = 0; k0 < K; k0 += 16) {
        float4 av = make_float4(0.f, 0.f, 0.f, 0.f);
        int gr = bm + a_row;
        if (gr < M) av = *(const float4*)&A[(size_t)gr * K + k0 + a_col];
        As[a_col + 0][a_row] = av.x;
        As[a_col + 1][a_row] = av.y;
        As[a_col + 2][a_row] = av.z;
        As[a_col + 3][a_row] = av.w;
        #pragma unroll
        for (int i = 0; i < 2; i++) {
            int f = tid + i * 256;
            int br = f >> 5, bc = (f & 31) * 4;
            *(float4*)&Bs[br][bc] = *(const float4*)&B[(size_t)(k0 + br) * N + bn + bc];
        }
        __syncthreads();
        #pragma unroll
        for (int k = 0; k < 16; k++) {
            float a[8];
            *(float4*)&a[0] = *(const float4*)&As[k][row0];
            *(float4*)&a[4] = *(const float4*)&As[k][row0 + 4];
            unsigned long long b0 = *(const unsigned long long*)&Bs[k][col0];
            unsigned long long b1 = *(const unsigned long long*)&Bs[k][col0 + 2];
            #pragma unroll
            for (int i = 0; i < 8; i++) {
                unsigned long long aa = pack2(a[i], a[i]);
                FMA_F32X2(acc[i][0], aa, b0, acc[i][0]);
                FMA_F32X2(acc[i][1], aa, b1, acc[i][1]);
            }
        }
        __syncthreads();
    }

    int c = bn + col0;
    float bv[4];
    bv[0] = bias[c + 0]; bv[1] = bias[c + 1]; bv[2] = bias[c + 2]; bv[3] = bias[c + 3];
    #pragma unroll
    for (int i = 0; i < 8; i++) {
        int r = bm + row0 + i;
        if (r >= M) break;
        float v[4];
        unpack2(acc[i][0], v[0], v[1]);
        unpack2(acc[i][1], v[2], v[3]);
        #pragma unroll
        for (int j = 0; j < 4; j++) v[j] += bv[j];
        if (Cin) {
            #pragma unroll
            for (int j = 0; j < 4; j++) v[j] += Cin[(size_t)r * N + c + j];
        }
        *(float4*)&Cout[(size_t)r * N + c] = make_float4(v[0], v[1], v[2], v[3]);
    }
}

// ---------------- per-node pre kernel: LN + leaky + msg precompute ----------------
__global__ __launch_bounds__(128) void node_pre_kernel(
    const float* __restrict__ ln_g, const float* __restrict__ ln_b,
    const float* __restrict__ tptr, int li)
{
    __shared__ float s[8];
    int n = blockIdx.x, f = threadIdx.x;
    float x = g_h[n * HID + f];
    float mu = blockSum(x, s) * (1.f / HID);
    float d = x - mu;
    float var = blockSum(d * d, s) * (1.f / HID);
    float y = d * rsqrtf(var + 1e-5f) * ln_g[li * HID + f] + ln_b[li * HID + f];
    float r = (y > 0.f) ? y : 0.01f * y;           // leaky_relu(0.01)
    g_r[n * HID + f] = r;
    float nrm2 = blockSum(r * r, s);
    if (f == 0) g_rnorm[n] = sqrtf(nrm2);
    float t = tptr[li];
    float m = fmaxf(y, 0.f) + 1e-7f;               // relu(leaky(y)) == relu(y)
    float q = expf(m * t);
    g_Q[n * HID + f] = q;
    g_P[n * HID + f] = m * q;
}

// ---------------- aggregation: softmax-agg + MessageNorm + residual ----------------
__global__ __launch_bounds__(128) void aggregate_kernel(
    const float* __restrict__ scptr, int li)
{
    __shared__ float s[8];
    int n = blockIdx.x, f = threadIdx.x;
    int st = g_rowptr[n], en = g_rowptr[n + 1];
    float num = 0.f, den = 0.f;
    int e = st;
    for (; e + 1 < en; e += 2) {
        int s0 = __ldg(&g_col[e]);
        int s1 = __ldg(&g_col[e + 1]);
        float p0 = g_P[s0 * HID + f], q0 = g_Q[s0 * HID + f];
        float p1 = g_P[s1 * HID + f], q1 = g_Q[s1 * HID + f];
        num += p0 + p1;
        den += q0 + q1;
    }
    if (e < en) {
        int s0 = __ldg(&g_col[e]);
        num += g_P[s0 * HID + f];
        den += g_Q[s0 * HID + f];
    }
    float agg = num / (den + 1e-16f);
    float n2 = blockSum(agg * agg, s);
    float inv = 1.f / fmaxf(sqrtf(n2), 1e-12f);
    float out = g_r[n * HID + f] + agg * inv * g_rnorm[n] * scptr[li];
    g_out[n * HID + f] = out;
}

// ---------------- LN(256) + relu on z1 ----------------
__global__ __launch_bounds__(256) void ln_relu_kernel(
    const float* __restrict__ mg, const float* __restrict__ mb, int li)
{
    __shared__ float s[8];
    int n = blockIdx.x, f = threadIdx.x;
    float x = g_z1[n * H2 + f];
    float mu = blockSum(x, s) * (1.f / H2);
    float d = x - mu;
    float var = blockSum(d * d, s) * (1.f / H2);
    float y = d * rsqrtf(var + 1e-5f) * mg[li * H2 + f] + mb[li * H2 + f];
    g_a[n * H2 + f] = fmaxf(y, 0.f);
}

// ---------------- final LN + leaky + pooled accumulation ----------------
__global__ void zero_pool_kernel() {
    int i = blockIdx.x * blockDim.x + threadIdx.x;
    if (i < N_GRAPH * HID) g_gsum[i] = 0.f;
    if (i < N_GRAPH) g_cnt[i] = 0.f;
}
__global__ __launch_bounds__(128) void final_kernel(
    const float* __restrict__ fn_g, const float* __restrict__ fn_b,
    const int* __restrict__ batch)
{
    __shared__ float s[8];
    int n = blockIdx.x, f = threadIdx.x;
    float x = g_h[n * HID + f];
    float mu = blockSum(x, s) * (1.f / HID);
    float d = x - mu;
    float var = blockSum(d * d, s) * (1.f / HID);
    float y = d * rsqrtf(var + 1e-5f) * fn_g[f] + fn_b[f];
    float v = (y > 0.f) ? y : 0.01f * y;
    int g = batch[n];
    atomicAdd(&g_gsum[g * HID + f], v);
    if (f == 0) atomicAdd(&g_cnt[g], 1.0f);
}
__global__ void pool_div_kernel(float* __restrict__ out) {
    int i = blockIdx.x * blockDim.x + threadIdx.x;
    if (i < N_GRAPH * HID) {
        int g = i >> 7;
        out[i] = g_gsum[i] / fmaxf(g_cnt[g], 1.0f);
    }
}

// ---------------- host launch ----------------
extern "C" void kernel_launch(void* const* d_in, const int* in_sizes, int n_in,
                              void* d_out, int out_size)
{
    const float* x     = (const float*)d_in[0];
    const int*   ei    = (const int*)d_in[1];   // [2,E] int32 (src row 0, dst row 1)
    const int*   batch = (const int*)d_in[2];
    const float* enc_W = (const float*)d_in[3];
    const float* enc_b = (const float*)d_in[4];
    const float* ln_g  = (const float*)d_in[5];
    const float* ln_b  = (const float*)d_in[6];
    const float* t     = (const float*)d_in[7];
    const float* sc    = (const float*)d_in[8];
    const float* W1    = (const float*)d_in[9];
    const float* b1    = (const float*)d_in[10];
    const float* mg    = (const float*)d_in[11];
    const float* mb    = (const float*)d_in[12];
    const float* W2    = (const float*)d_in[13];
    const float* b2    = (const float*)d_in[14];
    const float* fn_g  = (const float*)d_in[15];
    const float* fn_b  = (const float*)d_in[16];
    float* out = (float*)d_out;

    float *p_h, *p_out, *p_z1, *p_a;
    cudaGetSymbolAddress((void**)&p_h,   g_h);
    cudaGetSymbolAddress((void**)&p_out, g_out);
    cudaGetSymbolAddress((void**)&p_z1,  g_z1);
    cudaGetSymbolAddress((void**)&p_a,   g_a);

    const int MB = (N_NODES + 63) / 64;   // 157 row-blocks

    // CSR (edge_index is an input, so rebuild each call — ~20us)
    zero_csr_kernel<<<(N_NODES + 255) / 256, 256>>>();
    csr_count_kernel<<<(N_EDGES + 255) / 256, 256>>>(ei);
    scan_kernel<<<1, 1024>>>();
    csr_fill_kernel<<<(N_EDGES + 255) / 256, 256>>>(ei);

    // encoder: h = x @ enc_W + enc_b
    gemm_kernel<<<dim3(1, MB), 256>>>(x, enc_W, enc_b, nullptr, p_h,
                                      N_NODES, HID, HID);

    for (int li = 0; li < N_LAYER; li++) {
        node_pre_kernel<<<N_NODES, 128>>>(ln_g, ln_b, t, li);
        aggregate_kernel<<<N_NODES, 128>>>(sc, li);
        // z1 = out @ W1 + b1
        gemm_kernel<<<dim3(2, MB), 256>>>(p_out, W1 + (size_t)li * HID * H2,
                                          b1 + (size_t)li * H2, nullptr, p_z1,
                                          N_NODES, H2, HID);
        ln_relu_kernel<<<N_NODES, 256>>>(mg, mb, li);
        // h += a @ W2 + b2
        gemm_kernel<<<dim3(1, MB), 256>>>(p_a, W2 + (size_t)li * H2 * HID,
                                          b2 + (size_t)li * HID, p_h, p_h,
                                          N_NODES, HID, H2);
    }

    zero_pool_kernel<<<(N_GRAPH * HID + 255) / 256, 256>>>();
    final_kernel<<<N_NODES, 128>>>(fn_g, fn_b, batch);
    pool_div_kernel<<<(N_GRAPH * HID + 255) / 256, 256>>>(out);
}

// round 4
// speedup vs baseline: 1.1734x; 1.1734x over previous
#include <cuda_runtime.h>
#include <cuda_bf16.h>
#include <math.h>

#define N_NODES 10000
#define N_EDGES 160000
#define N_GRAPH 64
#define HID     128
#define H2      256
#define N_LAYER 14

// ---------------- device scratch (no allocations allowed) ----------------
__device__ float g_h[N_NODES * HID];
__device__ float g_r[N_NODES * HID];
__device__ float g_rnorm[N_NODES];
__device__ float g_Q[N_NODES * HID];
__device__ float g_P[N_NODES * HID];
__device__ float g_out[N_NODES * HID];
__device__ int   g_deg[N_NODES];
__device__ int   g_rowptr[N_NODES + 1];
__device__ int   g_cursor[N_NODES];
__device__ int   g_col[N_EDGES];
__device__ float g_gsum[N_GRAPH * HID];
__device__ float g_cnt[N_GRAPH];

// ---------------- helpers ----------------
__device__ __forceinline__ unsigned long long pack2(float lo, float hi) {
    unsigned long long r;
    asm("mov.b64 %0, {%1,%2};" : "=l"(r) : "f"(lo), "f"(hi));
    return r;
}
__device__ __forceinline__ void unpack2(unsigned long long v, float& lo, float& hi) {
    asm("mov.b64 {%0,%1}, %2;" : "=f"(lo), "=f"(hi) : "l"(v));
}
#define FMA_F32X2(d, a, b, c) \
    asm("fma.rn.f32x2 %0, %1, %2, %3;" : "=l"(d) : "l"(a), "l"(b), "l"(c))

__device__ __forceinline__ float warpSum(float v) {
    #pragma unroll
    for (int o = 16; o; o >>= 1) v += __shfl_xor_sync(0xffffffffu, v, o);
    return v;
}

// block-wide sum, result broadcast. blockDim multiple of 32, <=256.
__device__ __forceinline__ float blockSum(float v, float* s) {
    #pragma unroll
    for (int o = 16; o; o >>= 1) v += __shfl_down_sync(0xffffffffu, v, o);
    __syncthreads();
    if ((threadIdx.x & 31) == 0) s[threadIdx.x >> 5] = v;
    __syncthreads();
    int nw = blockDim.x >> 5;
    float t = 0.f;
    for (int i = 0; i < nw; i++) t += s[i];
    return t;
}

// ---------------- CSR construction ----------------
__global__ void zero_csr_kernel() {
    int i = blockIdx.x * blockDim.x + threadIdx.x;
    if (i < N_NODES) g_deg[i] = 0;
}
__global__ void csr_count_kernel(const int* __restrict__ ei) {
    int e = blockIdx.x * blockDim.x + threadIdx.x;
    if (e < N_EDGES) atomicAdd(&g_deg[ei[N_EDGES + e]], 1);
}
__global__ void scan_kernel() {
    __shared__ int s[1024];
    const int CH = 10;
    int t = threadIdx.x;
    int base = t * CH;
    int local[CH];
    int sum = 0;
    #pragma unroll
    for (int j = 0; j < CH; j++) {
        int idx = base + j;
        int v = (idx < N_NODES) ? g_deg[idx] : 0;
        local[j] = sum;
        sum += v;
    }
    s[t] = sum;
    __syncthreads();
    for (int off = 1; off < 1024; off <<= 1) {
        int v = (t >= off) ? s[t - off] : 0;
        __syncthreads();
        s[t] += v;
        __syncthreads();
    }
    int offset = (t > 0) ? s[t - 1] : 0;
    #pragma unroll
    for (int j = 0; j < CH; j++) {
        int idx = base + j;
        if (idx < N_NODES) {
            g_rowptr[idx] = offset + local[j];
            g_cursor[idx] = offset + local[j];
        }
    }
    if (t == 1023) g_rowptr[N_NODES] = s[1023];
}
__global__ void csr_fill_kernel(const int* __restrict__ ei) {
    int e = blockIdx.x * blockDim.x + threadIdx.x;
    if (e < N_EDGES) {
        int d = ei[N_EDGES + e];
        int p = atomicAdd(&g_cursor[d], 1);
        g_col[p] = ei[e];
    }
}

// ---------------- encoder GEMM: C = A@B + bias ----------------
// A:[M,128], B:[128,128]. BM=64, BN=128, BK=16, 256 threads.
__global__ __launch_bounds__(256) void gemm_kernel(
    const float* __restrict__ A, const float* __restrict__ B,
    const float* __restrict__ bias, float* __restrict__ Cout,
    int M, int N, int K)
{
    __shared__ float As[16][64];
    __shared__ float Bs[16][128];
    int tid = threadIdx.x;
    int bm = blockIdx.y * 64;
    int bn = blockIdx.x * 128;
    int tr = tid >> 5;
    int tc = tid & 31;
    int row0 = tr * 8, col0 = tc * 4;

    unsigned long long acc[8][2];
    #pragma unroll
    for (int i = 0; i < 8; i++) { acc[i][0] = 0ull; acc[i][1] = 0ull; }

    int a_row = tid >> 2;
    int a_col = (tid & 3) * 4;

    for (int k0 = 0; k0 < K; k0 += 16) {
        float4 av = make_float4(0.f, 0.f, 0.f, 0.f);
        int gr = bm + a_row;
        if (gr < M) av = *(const float4*)&A[(size_t)gr * K + k0 + a_col];
        As[a_col + 0][a_row] = av.x;
        As[a_col + 1][a_row] = av.y;
        As[a_col + 2][a_row] = av.z;
        As[a_col + 3][a_row] = av.w;
        #pragma unroll
        for (int i = 0; i < 2; i++) {
            int f = tid + i * 256;
            int br = f >> 5, bc = (f & 31) * 4;
            *(float4*)&Bs[br][bc] = *(const float4*)&B[(size_t)(k0 + br) * N + bn + bc];
        }
        __syncthreads();
        #pragma unroll
        for (int k = 0; k < 16; k++) {
            float a[8];
            *(float4*)&a[0] = *(const float4*)&As[k][row0];
            *(float4*)&a[4] = *(const float4*)&As[k][row0 + 4];
            ulonglong2 bb = *(const ulonglong2*)&Bs[k][col0];
            #pragma unroll
            for (int i = 0; i < 8; i++) {
                unsigned long long aa = pack2(a[i], a[i]);
                FMA_F32X2(acc[i][0], aa, bb.x, acc[i][0]);
                FMA_F32X2(acc[i][1], aa, bb.y, acc[i][1]);
            }
        }
        __syncthreads();
    }

    int c = bn + col0;
    float4 bv = *(const float4*)&bias[c];
    #pragma unroll
    for (int i = 0; i < 8; i++) {
        int r = bm + row0 + i;
        if (r >= M) break;
        float v0, v1, v2, v3;
        unpack2(acc[i][0], v0, v1);
        unpack2(acc[i][1], v2, v3);
        float4 o = make_float4(v0 + bv.x, v1 + bv.y, v2 + bv.z, v3 + bv.w);
        *(float4*)&Cout[(size_t)r * N + c] = o;
    }
}

// ---------------- per-node pre kernel (layer 0 only) ----------------
__global__ __launch_bounds__(128) void node_pre_kernel(
    const float* __restrict__ ln_g, const float* __restrict__ ln_b,
    const float* __restrict__ tptr, int li)
{
    __shared__ float s[8];
    int n = blockIdx.x, f = threadIdx.x;
    float x = g_h[n * HID + f];
    float mu = blockSum(x, s) * (1.f / HID);
    float d = x - mu;
    float var = blockSum(d * d, s) * (1.f / HID);
    float y = d * rsqrtf(var + 1e-5f) * ln_g[li * HID + f] + ln_b[li * HID + f];
    float r = (y > 0.f) ? y : 0.01f * y;
    g_r[n * HID + f] = r;
    float nrm2 = blockSum(r * r, s);
    if (f == 0) g_rnorm[n] = sqrtf(nrm2);
    float t = tptr[li];
    float m = fmaxf(y, 0.f) + 1e-7f;
    float q = expf(m * t);
    g_Q[n * HID + f] = q;
    g_P[n * HID + f] = m * q;
}

// ---------------- aggregation: softmax-agg + MessageNorm + residual ----------------
__global__ __launch_bounds__(128) void aggregate_kernel(
    const float* __restrict__ scptr, int li)
{
    __shared__ float s[8];
    int n = blockIdx.x, f = threadIdx.x;
    int st = g_rowptr[n], en = g_rowptr[n + 1];
    float num = 0.f, den = 0.f;
    int e = st;
    for (; e + 3 < en; e += 4) {
        int s0 = __ldg(&g_col[e]);
        int s1 = __ldg(&g_col[e + 1]);
        int s2 = __ldg(&g_col[e + 2]);
        int s3 = __ldg(&g_col[e + 3]);
        float p0 = g_P[s0 * HID + f], q0 = g_Q[s0 * HID + f];
        float p1 = g_P[s1 * HID + f], q1 = g_Q[s1 * HID + f];
        float p2 = g_P[s2 * HID + f], q2 = g_Q[s2 * HID + f];
        float p3 = g_P[s3 * HID + f], q3 = g_Q[s3 * HID + f];
        num += (p0 + p1) + (p2 + p3);
        den += (q0 + q1) + (q2 + q3);
    }
    for (; e < en; e++) {
        int s0 = __ldg(&g_col[e]);
        num += g_P[s0 * HID + f];
        den += g_Q[s0 * HID + f];
    }
    float agg = num / (den + 1e-16f);
    float n2 = blockSum(agg * agg, s);
    float inv = 1.f / fmaxf(sqrtf(n2), 1e-12f);
    float out = g_r[n * HID + f] + agg * inv * g_rnorm[n] * scptr[li];
    g_out[n * HID + f] = out;
}

// ---------------- fused layer: GEMM1 + LN+ReLU + GEMM2 + residual + next-layer pre --
// grid 157 x 256 threads, 64 rows per block.
// smem: z1s[64][260] | As[16][64] | Bs[16*256]  = 21760 floats = 87040 bytes
#define Z1_STRIDE 260
#define HS_STRIDE 132
#define FUSED_SMEM ((64 * 260 + 16 * 64 + 16 * 256) * 4)

__global__ void __launch_bounds__(256, 2) fused_layer_kernel(
    const float* __restrict__ W1, const float* __restrict__ b1,
    const float* __restrict__ mg, const float* __restrict__ mb,
    const float* __restrict__ W2, const float* __restrict__ b2,
    const float* __restrict__ ln_g, const float* __restrict__ ln_b,
    const float* __restrict__ tptr, int li, int do_pre)
{
    extern __shared__ float sm[];
    float* z1s = sm;                       // [64][260]
    float* As  = sm + 64 * Z1_STRIDE;      // [16][64]
    float* Bs  = As + 16 * 64;             // [16][256] (stage A) / [16][128] (stage C)

    const int tid  = threadIdx.x;
    const int warp = tid >> 5, lane = tid & 31;
    const int bm   = blockIdx.x * 64;
    const int row0 = warp * 8;
    const int c0   = lane * 4;

    // ======== Stage A: z1 = out @ W1 + b1  (64x256, K=128) ========
    unsigned long long acc[8][4];
    #pragma unroll
    for (int i = 0; i < 8; i++)
        #pragma unroll
        for (int j = 0; j < 4; j++) acc[i][j] = 0ull;

    const float* Wl1 = W1 + (size_t)li * HID * H2;
    const int ar = tid >> 2;
    const int ac = (tid & 3) * 4;

    for (int k0 = 0; k0 < HID; k0 += 16) {
        float4 av = make_float4(0.f, 0.f, 0.f, 0.f);
        if (bm + ar < N_NODES)
            av = *(const float4*)&g_out[(size_t)(bm + ar) * HID + k0 + ac];
        As[(ac + 0) * 64 + ar] = av.x;
        As[(ac + 1) * 64 + ar] = av.y;
        As[(ac + 2) * 64 + ar] = av.z;
        As[(ac + 3) * 64 + ar] = av.w;
        #pragma unroll
        for (int i = 0; i < 4; i++) {
            int idx = tid + i * 256;  // float4 index 0..1023
            *(float4*)&Bs[idx * 4] = *(const float4*)&Wl1[(size_t)k0 * H2 + idx * 4];
        }
        __syncthreads();
        #pragma unroll
        for (int k = 0; k < 16; k++) {
            float a[8];
            *(float4*)&a[0] = *(const float4*)&As[k * 64 + row0];
            *(float4*)&a[4] = *(const float4*)&As[k * 64 + row0 + 4];
            ulonglong2 bA = *(const ulonglong2*)&Bs[k * H2 + c0];
            ulonglong2 bB = *(const ulonglong2*)&Bs[k * H2 + 128 + c0];
            #pragma unroll
            for (int i = 0; i < 8; i++) {
                unsigned long long aa = pack2(a[i], a[i]);
                FMA_F32X2(acc[i][0], aa, bA.x, acc[i][0]);
                FMA_F32X2(acc[i][1], aa, bA.y, acc[i][1]);
                FMA_F32X2(acc[i][2], aa, bB.x, acc[i][2]);
                FMA_F32X2(acc[i][3], aa, bB.y, acc[i][3]);
            }
        }
        __syncthreads();
    }
    // write z1 tile (+bias) to smem
    {
        float4 bvA = *(const float4*)&b1[(size_t)li * H2 + c0];
        float4 bvB = *(const float4*)&b1[(size_t)li * H2 + 128 + c0];
        #pragma unroll
        for (int i = 0; i < 8; i++) {
            float v0, v1, v2, v3;
            unpack2(acc[i][0], v0, v1);
            unpack2(acc[i][1], v2, v3);
            float4 oA = make_float4(v0 + bvA.x, v1 + bvA.y, v2 + bvA.z, v3 + bvA.w);
            unpack2(acc[i][2], v0, v1);
            unpack2(acc[i][3], v2, v3);
            float4 oB = make_float4(v0 + bvB.x, v1 + bvB.y, v2 + bvB.z, v3 + bvB.w);
            *(float4*)&z1s[(row0 + i) * Z1_STRIDE + c0]       = oA;
            *(float4*)&z1s[(row0 + i) * Z1_STRIDE + 128 + c0] = oB;
        }
    }
    __syncthreads();

    // ======== LayerNorm(256) + ReLU in smem; warp handles rows row0..row0+7 ====
    {
        float4 gA = *(const float4*)&mg[(size_t)li * H2 + c0];
        float4 gB = *(const float4*)&mg[(size_t)li * H2 + 128 + c0];
        float4 bA = *(const float4*)&mb[(size_t)li * H2 + c0];
        float4 bB = *(const float4*)&mb[(size_t)li * H2 + 128 + c0];
        #pragma unroll
        for (int i = 0; i < 8; i++) {
            float* rp = &z1s[(row0 + i) * Z1_STRIDE];
            float4 vA = *(const float4*)&rp[c0];
            float4 vB = *(const float4*)&rp[128 + c0];
            float s1 = (vA.x + vA.y) + (vA.z + vA.w) + (vB.x + vB.y) + (vB.z + vB.w);
            float s2 = vA.x * vA.x + vA.y * vA.y + vA.z * vA.z + vA.w * vA.w
                     + vB.x * vB.x + vB.y * vB.y + vB.z * vB.z + vB.w * vB.w;
            s1 = warpSum(s1);
            s2 = warpSum(s2);
            float mu  = s1 * (1.f / H2);
            float var = s2 * (1.f / H2) - mu * mu;
            float is  = rsqrtf(var + 1e-5f);
            vA.x = fmaxf((vA.x - mu) * is * gA.x + bA.x, 0.f);
            vA.y = fmaxf((vA.y - mu) * is * gA.y + bA.y, 0.f);
            vA.z = fmaxf((vA.z - mu) * is * gA.z + bA.z, 0.f);
            vA.w = fmaxf((vA.w - mu) * is * gA.w + bA.w, 0.f);
            vB.x = fmaxf((vB.x - mu) * is * gB.x + bB.x, 0.f);
            vB.y = fmaxf((vB.y - mu) * is * gB.y + bB.y, 0.f);
            vB.z = fmaxf((vB.z - mu) * is * gB.z + bB.z, 0.f);
            vB.w = fmaxf((vB.w - mu) * is * gB.w + bB.w, 0.f);
            *(float4*)&rp[c0]       = vA;
            *(float4*)&rp[128 + c0] = vB;
        }
    }
    __syncthreads();

    // ======== Stage C: h' = h + a @ W2 + b2  (64x128, K=256) ========
    unsigned long long acc2[8][2];
    #pragma unroll
    for (int i = 0; i < 8; i++) { acc2[i][0] = 0ull; acc2[i][1] = 0ull; }

    const float* Wl2 = W2 + (size_t)li * H2 * HID;
    for (int k0 = 0; k0 < H2; k0 += 16) {
        #pragma unroll
        for (int i = 0; i < 2; i++) {
            int idx = tid + i * 256;  // float4 index 0..511
            *(float4*)&Bs[idx * 4] = *(const float4*)&Wl2[(size_t)k0 * HID + idx * 4];
        }
        __syncthreads();
        #pragma unroll
        for (int k4 = 0; k4 < 4; k4++) {
            float4 a4[8];
            #pragma unroll
            for (int i = 0; i < 8; i++)
                a4[i] = *(const float4*)&z1s[(row0 + i) * Z1_STRIDE + k0 + k4 * 4];
            #pragma unroll
            for (int kk = 0; kk < 4; kk++) {
                ulonglong2 bb = *(const ulonglong2*)&Bs[(k4 * 4 + kk) * HID + c0];
                #pragma unroll
                for (int i = 0; i < 8; i++) {
                    float avv = (kk == 0) ? a4[i].x : (kk == 1) ? a4[i].y
                              : (kk == 2) ? a4[i].z : a4[i].w;
                    unsigned long long aa = pack2(avv, avv);
                    FMA_F32X2(acc2[i][0], aa, bb.x, acc2[i][0]);
                    FMA_F32X2(acc2[i][1], aa, bb.y, acc2[i][1]);
                }
            }
        }
        __syncthreads();
    }

    // epilogue: residual add, write g_h, stash row tile in smem (reuse z1s region)
    float* hs = sm;  // [64][132]
    {
        float4 bv = *(const float4*)&b2[(size_t)li * HID + c0];
        #pragma unroll
        for (int i = 0; i < 8; i++) {
            int r = bm + row0 + i;
            float v0, v1, v2, v3;
            unpack2(acc2[i][0], v0, v1);
            unpack2(acc2[i][1], v2, v3);
            float4 o = make_float4(v0 + bv.x, v1 + bv.y, v2 + bv.z, v3 + bv.w);
            if (r < N_NODES) {
                float4 hold = *(const float4*)&g_h[(size_t)r * HID + c0];
                o.x += hold.x; o.y += hold.y; o.z += hold.z; o.w += hold.w;
                *(float4*)&g_h[(size_t)r * HID + c0] = o;
            }
            *(float4*)&hs[(row0 + i) * HS_STRIDE + c0] = o;
        }
    }
    __syncthreads();

    // ======== next-layer node_pre fused (LN(128) + leaky + msg precompute) ====
    if (do_pre) {
        int ln = li + 1;
        float4 gv = *(const float4*)&ln_g[(size_t)ln * HID + c0];
        float4 bb = *(const float4*)&ln_b[(size_t)ln * HID + c0];
        float t = tptr[ln];
        #pragma unroll
        for (int i = 0; i < 8; i++) {
            int r = bm + row0 + i;       // uniform across warp
            if (r >= N_NODES) continue;
            float4 v = *(const float4*)&hs[(row0 + i) * HS_STRIDE + c0];
            float s1 = (v.x + v.y) + (v.z + v.w);
            float s2 = v.x * v.x + v.y * v.y + v.z * v.z + v.w * v.w;
            s1 = warpSum(s1);
            s2 = warpSum(s2);
            float mu  = s1 * (1.f / HID);
            float var = s2 * (1.f / HID) - mu * mu;
            float is  = rsqrtf(var + 1e-5f);
            float y0 = (v.x - mu) * is * gv.x + bb.x;
            float y1 = (v.y - mu) * is * gv.y + bb.y;
            float y2 = (v.z - mu) * is * gv.z + bb.z;
            float y3 = (v.w - mu) * is * gv.w + bb.w;
            float4 rr = make_float4((y0 > 0.f) ? y0 : 0.01f * y0,
                                    (y1 > 0.f) ? y1 : 0.01f * y1,
                                    (y2 > 0.f) ? y2 : 0.01f * y2,
                                    (y3 > 0.f) ? y3 : 0.01f * y3);
            float m0 = fmaxf(y0, 0.f) + 1e-7f;
            float m1 = fmaxf(y1, 0.f) + 1e-7f;
            float m2 = fmaxf(y2, 0.f) + 1e-7f;
            float m3 = fmaxf(y3, 0.f) + 1e-7f;
            float4 qq = make_float4(expf(m0 * t), expf(m1 * t), expf(m2 * t), expf(m3 * t));
            float4 pp = make_float4(m0 * qq.x, m1 * qq.y, m2 * qq.z, m3 * qq.w);
            *(float4*)&g_r[(size_t)r * HID + c0] = rr;
            *(float4*)&g_Q[(size_t)r * HID + c0] = qq;
            *(float4*)&g_P[(size_t)r * HID + c0] = pp;
            float r2 = rr.x * rr.x + rr.y * rr.y + rr.z * rr.z + rr.w * rr.w;
            r2 = warpSum(r2);
            if (lane == 0) g_rnorm[r] = sqrtf(r2);
        }
    }
}

// ---------------- final LN + leaky + pooled accumulation ----------------
__global__ void zero_pool_kernel() {
    int i = blockIdx.x * blockDim.x + threadIdx.x;
    if (i < N_GRAPH * HID) g_gsum[i] = 0.f;
    if (i < N_GRAPH) g_cnt[i] = 0.f;
}
__global__ __launch_bounds__(128) void final_kernel(
    const float* __restrict__ fn_g, const float* __restrict__ fn_b,
    const int* __restrict__ batch)
{
    __shared__ float s[8];
    int n = blockIdx.x, f = threadIdx.x;
    float x = g_h[n * HID + f];
    float mu = blockSum(x, s) * (1.f / HID);
    float d = x - mu;
    float var = blockSum(d * d, s) * (1.f / HID);
    float y = d * rsqrtf(var + 1e-5f) * fn_g[f] + fn_b[f];
    float v = (y > 0.f) ? y : 0.01f * y;
    int g = batch[n];
    atomicAdd(&g_gsum[g * HID + f], v);
    if (f == 0) atomicAdd(&g_cnt[g], 1.0f);
}
__global__ void pool_div_kernel(float* __restrict__ out) {
    int i = blockIdx.x * blockDim.x + threadIdx.x;
    if (i < N_GRAPH * HID) {
        int g = i >> 7;
        out[i] = g_gsum[i] / fmaxf(g_cnt[g], 1.0f);
    }
}

// ---------------- host launch ----------------
extern "C" void kernel_launch(void* const* d_in, const int* in_sizes, int n_in,
                              void* d_out, int out_size)
{
    const float* x     = (const float*)d_in[0];
    const int*   ei    = (const int*)d_in[1];
    const int*   batch = (const int*)d_in[2];
    const float* enc_W = (const float*)d_in[3];
    const float* enc_b = (const float*)d_in[4];
    const float* ln_g  = (const float*)d_in[5];
    const float* ln_b  = (const float*)d_in[6];
    const float* t     = (const float*)d_in[7];
    const float* sc    = (const float*)d_in[8];
    const float* W1    = (const float*)d_in[9];
    const float* b1    = (const float*)d_in[10];
    const float* mg    = (const float*)d_in[11];
    const float* mb    = (const float*)d_in[12];
    const float* W2    = (const float*)d_in[13];
    const float* b2    = (const float*)d_in[14];
    const float* fn_g  = (const float*)d_in[15];
    const float* fn_b  = (const float*)d_in[16];
    float* out = (float*)d_out;

    float* p_h;
    cudaGetSymbolAddress((void**)&p_h, g_h);

    cudaFuncSetAttribute(fused_layer_kernel,
                         cudaFuncAttributeMaxDynamicSharedMemorySize, FUSED_SMEM);

    const int MB = (N_NODES + 63) / 64;   // 157 row-blocks

    // CSR build (~20us)
    zero_csr_kernel<<<(N_NODES + 255) / 256, 256>>>();
    csr_count_kernel<<<(N_EDGES + 255) / 256, 256>>>(ei);
    scan_kernel<<<1, 1024>>>();
    csr_fill_kernel<<<(N_EDGES + 255) / 256, 256>>>(ei);

    // encoder: h = x @ enc_W + enc_b
    gemm_kernel<<<dim3(1, MB), 256>>>(x, enc_W, enc_b, p_h, N_NODES, HID, HID);
    // pre for layer 0
    node_pre_kernel<<<N_NODES, 128>>>(ln_g, ln_b, t, 0);

    for (int li = 0; li < N_LAYER; li++) {
        aggregate_kernel<<<N_NODES, 128>>>(sc, li);
        fused_layer_kernel<<<MB, 256, FUSED_SMEM>>>(
            W1, b1, mg, mb, W2, b2, ln_g, ln_b, t, li, (li < N_LAYER - 1) ? 1 : 0);
    }

    zero_pool_kernel<<<(N_GRAPH * HID + 255) / 256, 256>>>();
    final_kernel<<<N_NODES, 128>>>(fn_g, fn_b, batch);
    pool_div_kernel<<<(N_GRAPH * HID + 255) / 256, 256>>>(out);
}